// round 3
// baseline (speedup 1.0000x reference)
#include <cuda_runtime.h>
#include <cstdint>
#include <cstddef>

// ---------------------------------------------------------------------------
// NonLocalBlock: B=16, C=64, H=W=64, C1=8, C2=32
// out = gamma * conv1x1(attn_out, w_last, b_last) + x
// ---------------------------------------------------------------------------

#define DINL __device__ __forceinline__

// packed f32x2 helpers (sm_103a: fma.rn.f32x2 doubles fp32 flops/instr)
DINL unsigned long long pk2(float lo, float hi) {
    unsigned long long r;
    asm("mov.b64 %0, {%1, %2};" : "=l"(r) : "f"(lo), "f"(hi));
    return r;
}
DINL void upk2(unsigned long long v, float& lo, float& hi) {
    asm("mov.b64 {%0, %1}, %2;" : "=f"(lo), "=f"(hi) : "l"(v));
}
DINL unsigned long long fma2(unsigned long long a, unsigned long long b, unsigned long long c) {
    unsigned long long d;
    asm("fma.rn.f32x2 %0, %1, %2, %3;" : "=l"(d) : "l"(a), "l"(b), "l"(c));
    return d;
}
DINL unsigned long long mul2(unsigned long long a, unsigned long long b) {
    unsigned long long d;
    asm("mul.rn.f32x2 %0, %1, %2;" : "=l"(d) : "l"(a), "l"(b));
    return d;
}

// scratch (no allocation allowed -> __device__ globals)
__device__ float g_delta[16 * 4096 * 8];   // [b][n][8]
__device__ float g_phiP [16 * 8 * 1024];   // [b][c1][1024]  (pooled, pre-gather)
__device__ float g_gP   [16 * 1024 * 32];  // [b][m][32]     (pooled)

// ---------------------------------------------------------------------------
// Kernel 1: fused 3x conv1x1 (48 out ch) + 2x2 maxpool for phi/g.
// One thread per 2x1 pixel COLUMN of a pooled site; thread pairs (2t,2t+1)
// cover one 2x2 site and merge pooling via shfl_xor(1).
// grid (8,16), 256 threads -> 128 CTAs, full chip.
// ---------------------------------------------------------------------------
__global__ __launch_bounds__(256, 1) void conv_pool_kernel(
    const float* __restrict__ x,
    const float* __restrict__ w_delta, const float* __restrict__ b_delta,
    const float* __restrict__ w_phi,   const float* __restrict__ b_phi,
    const float* __restrict__ w_g,     const float* __restrict__ b_g)
{
    __shared__ ulonglong2 ws[64][12];   // [c][pair of 48 outputs]: 0-7 delta, 8-15 phi, 16-47 g
    __shared__ float bias[48];
    const int tid = threadIdx.x;

    for (int i = tid; i < 3072; i += 256) {
        int c = i / 48, o = i - c * 48;
        float w;
        if (o < 8)       w = w_delta[o * 64 + c];
        else if (o < 16) w = w_phi[(o - 8) * 64 + c];
        else             w = w_g[(o - 16) * 64 + c];
        ((float*)&ws[c][0])[o] = w;
    }
    if (tid < 48)
        bias[tid] = (tid < 8) ? b_delta[tid] : (tid < 16) ? b_phi[tid - 8] : b_g[tid - 16];
    __syncthreads();

    const int b   = blockIdx.y;
    const int t   = blockIdx.x * 256 + tid;   // 0..2047
    const int q   = t >> 1;                   // pooled site 0..1023
    const int col = t & 1;
    const int qy  = q >> 5, qx = q & 31;
    const int xcol = 2 * qx + col;
    const int row0 = 2 * qy;

    const float* xp = x + (size_t)b * 262144 + row0 * 64 + xcol;

    unsigned long long a0[24], a1[24];        // 48 ch for pixel(row0) / pixel(row0+1)
#pragma unroll
    for (int k = 0; k < 24; k++) { a0[k] = 0ull; a1[k] = 0ull; }

#pragma unroll 4
    for (int c = 0; c < 64; c++) {
        float xv0 = xp[c * 4096];             // coalesced across warp
        float xv1 = xp[c * 4096 + 64];
        unsigned long long x0 = pk2(xv0, xv0);
        unsigned long long x1 = pk2(xv1, xv1);
#pragma unroll
        for (int k = 0; k < 12; k++) {
            ulonglong2 w = ws[c][k];          // broadcast LDS.128
            a0[2*k]   = fma2(w.x, x0, a0[2*k]);
            a0[2*k+1] = fma2(w.y, x0, a0[2*k+1]);
            a1[2*k]   = fma2(w.x, x1, a1[2*k]);
            a1[2*k+1] = fma2(w.y, x1, a1[2*k+1]);
        }
    }

    float f0[48], f1[48];
#pragma unroll
    for (int k = 0; k < 24; k++) {
        upk2(a0[k], f0[2*k], f0[2*k+1]);
        upk2(a1[k], f1[2*k], f1[2*k+1]);
    }

    // delta: both pixels of this column
    float* dp0 = g_delta + ((size_t)(b * 4096 + row0 * 64 + xcol)) * 8;
#pragma unroll
    for (int j = 0; j < 8; j++) {
        dp0[j]          = f0[j] + bias[j];
        dp0[64 * 8 + j] = f1[j] + bias[j];
    }

    // pool within this column, then merge with partner column via shfl
    float pm[40];
#pragma unroll
    for (int j = 0; j < 40; j++) {
        float v = fmaxf(f0[8 + j], f1[8 + j]);
        pm[j] = fmaxf(v, __shfl_xor_sync(0xffffffffu, v, 1));
    }
    // bias commutes with max; col0 writes phi + g[0..15], col1 writes g[16..31]
    float* gp = g_gP + ((size_t)(b * 1024 + q)) * 32;
    if (col == 0) {
#pragma unroll
        for (int j = 0; j < 8; j++)
            g_phiP[(b * 8 + j) * 1024 + q] = pm[j] + bias[8 + j];
#pragma unroll
        for (int j = 0; j < 16; j++)
            gp[j] = pm[8 + j] + bias[16 + j];
    } else {
#pragma unroll
        for (int j = 16; j < 32; j++)
            gp[j] = pm[8 + j] + bias[16 + j];
    }
}

// ---------------------------------------------------------------------------
// Kernel 2: fused attention + final conv + residual.
// grid (8,16): 512 queries/CTA, 256 threads, 2 q/thread.
// Explicit 2-stage software pipeline: prefetch K/V of key m+1 into registers
// while computing key m, so the 29-cyc LDS latency is off the critical path.
// Single-pass softmax without max subtraction (scores O(10), exp safe in fp32).
// ---------------------------------------------------------------------------
__global__ __launch_bounds__(256, 1) void attn_kernel(
    const float* __restrict__ x,
    const float* __restrict__ w_last, const float* __restrict__ b_last,
    const float* __restrict__ gamma,  float* __restrict__ out)
{
    extern __shared__ float sm[];
    float* Vsm = sm;              // 1024*32 = 32768 floats (128 KB)
    float* Ksm = sm + 32768;      // 1024*8  =  8192 floats ( 32 KB)
    float* wl  = sm + 40960;      // 64*32   =  2048 floats (  8 KB)
    float* bl  = sm + 43008;      // 64

    const int tid = threadIdx.x;
    const int b   = blockIdx.y;

    {   // V: [1024][32] straight copy
        const float4* src = (const float4*)(g_gP + (size_t)b * 32768);
        float4* dst = (float4*)Vsm;
        for (int i = tid; i < 8192; i += 256) dst[i] = src[i];
    }
    // K gather with the reference's (1,0,2,3)-transpose batch mixing:
    // K[b][j][m] = phiP[(b*8+j)%16][(b*8+j)/16][m]
#pragma unroll
    for (int j = 0; j < 8; j++) {
        int idx = b * 8 + j;
        const float* src = g_phiP + (size_t)((idx & 15) * 8 + (idx >> 4)) * 1024;
        for (int m = tid; m < 1024; m += 256) Ksm[m * 8 + j] = src[m];
    }
    for (int i = tid; i < 2048; i += 256) wl[i] = w_last[i];
    if (tid < 64) bl[tid] = b_last[tid];
    __syncthreads();

    const int q0 = blockIdx.x * 512 + tid;
    const int q1 = q0 + 256;
    const ulonglong2* dq0 = (const ulonglong2*)(g_delta + ((size_t)b * 4096 + q0) * 8);
    const ulonglong2* dq1 = (const ulonglong2*)(g_delta + ((size_t)b * 4096 + q1) * 8);
    ulonglong2 qa = dq0[0], qb = dq0[1];
    ulonglong2 qc = dq1[0], qd = dq1[1];

    unsigned long long acc0[16], acc1[16];   // 2 x 32 fp32 accumulators as f32x2 pairs
#pragma unroll
    for (int k = 0; k < 16; k++) { acc0[k] = 0ull; acc1[k] = 0ull; }
    float l0 = 0.f, l1 = 0.f;

    const ulonglong2* K2 = (const ulonglong2*)Ksm;
    const ulonglong2* V2 = (const ulonglong2*)Vsm;

    // stage 0 preload
    ulonglong2 kA = K2[0], kB = K2[1];
    ulonglong2 v0 = V2[0], v1 = V2[1], v2 = V2[2], v3 = V2[3];
    ulonglong2 v4 = V2[4], v5 = V2[5], v6 = V2[6], v7 = V2[7];

#pragma unroll 2
    for (int m = 0; m < 1024; m++) {
        // prefetch key m+1 (wraps to 0 on last iter; value unused)
        const int mn = (m + 1) & 1023;
        ulonglong2 nkA = K2[2 * mn], nkB = K2[2 * mn + 1];
        const ulonglong2* nv = V2 + mn * 8;
        ulonglong2 nv0 = nv[0], nv1 = nv[1], nv2 = nv[2], nv3 = nv[3];
        ulonglong2 nv4 = nv[4], nv5 = nv[5], nv6 = nv[6], nv7 = nv[7];

        // QK for both queries
        unsigned long long p0 = mul2(qa.x, kA.x);
        p0 = fma2(qa.y, kA.y, p0);
        p0 = fma2(qb.x, kB.x, p0);
        p0 = fma2(qb.y, kB.y, p0);
        unsigned long long p1 = mul2(qc.x, kA.x);
        p1 = fma2(qc.y, kA.y, p1);
        p1 = fma2(qd.x, kB.x, p1);
        p1 = fma2(qd.y, kB.y, p1);
        float s0a, s0b, s1a, s1b;
        upk2(p0, s0a, s0b);
        upk2(p1, s1a, s1b);
        float e0 = __expf(s0a + s0b);
        float e1 = __expf(s1a + s1b);
        l0 += e0; l1 += e1;
        unsigned long long e0p = pk2(e0, e0);
        unsigned long long e1p = pk2(e1, e1);

        acc0[0]  = fma2(e0p, v0.x, acc0[0]);   acc1[0]  = fma2(e1p, v0.x, acc1[0]);
        acc0[1]  = fma2(e0p, v0.y, acc0[1]);   acc1[1]  = fma2(e1p, v0.y, acc1[1]);
        acc0[2]  = fma2(e0p, v1.x, acc0[2]);   acc1[2]  = fma2(e1p, v1.x, acc1[2]);
        acc0[3]  = fma2(e0p, v1.y, acc0[3]);   acc1[3]  = fma2(e1p, v1.y, acc1[3]);
        acc0[4]  = fma2(e0p, v2.x, acc0[4]);   acc1[4]  = fma2(e1p, v2.x, acc1[4]);
        acc0[5]  = fma2(e0p, v2.y, acc0[5]);   acc1[5]  = fma2(e1p, v2.y, acc1[5]);
        acc0[6]  = fma2(e0p, v3.x, acc0[6]);   acc1[6]  = fma2(e1p, v3.x, acc1[6]);
        acc0[7]  = fma2(e0p, v3.y, acc0[7]);   acc1[7]  = fma2(e1p, v3.y, acc1[7]);
        acc0[8]  = fma2(e0p, v4.x, acc0[8]);   acc1[8]  = fma2(e1p, v4.x, acc1[8]);
        acc0[9]  = fma2(e0p, v4.y, acc0[9]);   acc1[9]  = fma2(e1p, v4.y, acc1[9]);
        acc0[10] = fma2(e0p, v5.x, acc0[10]);  acc1[10] = fma2(e1p, v5.x, acc1[10]);
        acc0[11] = fma2(e0p, v5.y, acc0[11]);  acc1[11] = fma2(e1p, v5.y, acc1[11]);
        acc0[12] = fma2(e0p, v6.x, acc0[12]);  acc1[12] = fma2(e1p, v6.x, acc1[12]);
        acc0[13] = fma2(e0p, v6.y, acc0[13]);  acc1[13] = fma2(e1p, v6.y, acc1[13]);
        acc0[14] = fma2(e0p, v7.x, acc0[14]);  acc1[14] = fma2(e1p, v7.x, acc1[14]);
        acc0[15] = fma2(e0p, v7.y, acc0[15]);  acc1[15] = fma2(e1p, v7.y, acc1[15]);

        kA = nkA; kB = nkB;
        v0 = nv0; v1 = nv1; v2 = nv2; v3 = nv3;
        v4 = nv4; v5 = nv5; v6 = nv6; v7 = nv7;
    }

    // Fused epilogue: out[b,c,n] = gamma*(dot32(O_n, w_last[c]) + b_last[c]) + x[b,c,n]
    // with O = acc / l  =>  (gamma/l)*dot(acc, w) + gamma*b_last + x
    const float gm  = gamma[0];
    const float gi0 = __fdividef(gm, l0);
    const float gi1 = __fdividef(gm, l1);
    const float* xb = x   + (size_t)b * 262144;
    float*       ob = out + (size_t)b * 262144;
    const ulonglong2* wl2 = (const ulonglong2*)wl;

    for (int c = 0; c < 64; c++) {
        const ulonglong2* wr = wl2 + c * 8;
        ulonglong2 w0 = wr[0];
        unsigned long long s0 = mul2(acc0[0], w0.x);
        unsigned long long s1 = mul2(acc1[0], w0.x);
        s0 = fma2(acc0[1], w0.y, s0);
        s1 = fma2(acc1[1], w0.y, s1);
#pragma unroll
        for (int t = 1; t < 8; t++) {
            ulonglong2 w = wr[t];
            s0 = fma2(acc0[2*t],   w.x, s0);
            s1 = fma2(acc1[2*t],   w.x, s1);
            s0 = fma2(acc0[2*t+1], w.y, s0);
            s1 = fma2(acc1[2*t+1], w.y, s1);
        }
        float r0a, r0b, r1a, r1b;
        upk2(s0, r0a, r0b);
        upk2(s1, r1a, r1b);
        float base = gm * bl[c];
        ob[c * 4096 + q0] = fmaf(gi0, r0a + r0b, base + xb[c * 4096 + q0]);
        ob[c * 4096 + q1] = fmaf(gi1, r1a + r1b, base + xb[c * 4096 + q1]);
    }
}

// ---------------------------------------------------------------------------
extern "C" void kernel_launch(void* const* d_in, const int* in_sizes, int n_in,
                              void* d_out, int out_size)
{
    const float* x  = (const float*)d_in[0];
    const float* wd = (const float*)d_in[1];
    const float* bd = (const float*)d_in[2];
    const float* wp = (const float*)d_in[3];
    const float* bp = (const float*)d_in[4];
    const float* wg = (const float*)d_in[5];
    const float* bg = (const float*)d_in[6];
    const float* wl = (const float*)d_in[7];
    const float* bl = (const float*)d_in[8];
    const float* gm = (const float*)d_in[9];

    conv_pool_kernel<<<dim3(8, 16), 256>>>(x, wd, bd, wp, bp, wg, bg);

    const int shm = (32768 + 8192 + 2048 + 64) * 4;  // 172288 B
    cudaFuncSetAttribute(attn_kernel, cudaFuncAttributeMaxDynamicSharedMemorySize, shm);
    attn_kernel<<<dim3(8, 16), 256, shm>>>(x, wl, bl, gm, (float*)d_out);
}

// round 5
// speedup vs baseline: 1.7237x; 1.7237x over previous
#include <cuda_runtime.h>
#include <cstdint>
#include <cstddef>

// ---------------------------------------------------------------------------
// NonLocalBlock: B=16, C=64, H=W=64, C1=8, C2=32
// out = gamma * conv1x1(attn_out, w_last, b_last) + x
// ---------------------------------------------------------------------------

#define DINL __device__ __forceinline__

// packed f32x2 helpers (sm_103a: fma.rn.f32x2 doubles fp32 flops/instr)
DINL unsigned long long pk2(float lo, float hi) {
    unsigned long long r;
    asm("mov.b64 %0, {%1, %2};" : "=l"(r) : "f"(lo), "f"(hi));
    return r;
}
DINL void upk2(unsigned long long v, float& lo, float& hi) {
    asm("mov.b64 {%0, %1}, %2;" : "=f"(lo), "=f"(hi) : "l"(v));
}
DINL unsigned long long fma2(unsigned long long a, unsigned long long b, unsigned long long c) {
    unsigned long long d;
    asm("fma.rn.f32x2 %0, %1, %2, %3;" : "=l"(d) : "l"(a), "l"(b), "l"(c));
    return d;
}
DINL unsigned long long mul2(unsigned long long a, unsigned long long b) {
    unsigned long long d;
    asm("mul.rn.f32x2 %0, %1, %2;" : "=l"(d) : "l"(a), "l"(b));
    return d;
}
DINL float ex2(float x) {
    float r;
    asm("ex2.approx.f32 %0, %1;" : "=f"(r) : "f"(x));
    return r;
}

// scratch (no allocation allowed -> __device__ globals)
__device__ float g_delta[16 * 4096 * 8];   // [b][n][8]
__device__ float g_phiP [16 * 8 * 1024];   // [b][c1][1024]  (pooled, pre-gather)
__device__ float g_gP   [16 * 1024 * 32];  // [b][m][32]     (pooled)

// ---------------------------------------------------------------------------
// Kernel 1: fused 3x conv1x1 (48 out ch) + 2x2 maxpool for phi/g.
// One thread per 2x1 pixel column; thread pairs merge pooling via shfl_xor(1).
// grid (8,16), 256 threads -> 128 CTAs.
// ---------------------------------------------------------------------------
__global__ __launch_bounds__(256, 1) void conv_pool_kernel(
    const float* __restrict__ x,
    const float* __restrict__ w_delta, const float* __restrict__ b_delta,
    const float* __restrict__ w_phi,   const float* __restrict__ b_phi,
    const float* __restrict__ w_g,     const float* __restrict__ b_g)
{
    __shared__ ulonglong2 ws[64][12];   // [c][pair of 48 outputs]: 0-7 delta, 8-15 phi, 16-47 g
    __shared__ float bias[48];
    const int tid = threadIdx.x;

    for (int i = tid; i < 3072; i += 256) {
        int c = i / 48, o = i - c * 48;
        float w;
        if (o < 8)       w = w_delta[o * 64 + c];
        else if (o < 16) w = w_phi[(o - 8) * 64 + c];
        else             w = w_g[(o - 16) * 64 + c];
        ((float*)&ws[c][0])[o] = w;
    }
    if (tid < 48)
        bias[tid] = (tid < 8) ? b_delta[tid] : (tid < 16) ? b_phi[tid - 8] : b_g[tid - 16];
    __syncthreads();

    const int b   = blockIdx.y;
    const int t   = blockIdx.x * 256 + tid;   // 0..2047
    const int q   = t >> 1;                   // pooled site 0..1023
    const int col = t & 1;
    const int qy  = q >> 5, qx = q & 31;
    const int xcol = 2 * qx + col;
    const int row0 = 2 * qy;

    const float* xp = x + (size_t)b * 262144 + row0 * 64 + xcol;

    unsigned long long a0[24], a1[24];        // 48 ch for pixel(row0) / pixel(row0+1)
#pragma unroll
    for (int k = 0; k < 24; k++) { a0[k] = 0ull; a1[k] = 0ull; }

#pragma unroll 4
    for (int c = 0; c < 64; c++) {
        float xv0 = xp[c * 4096];             // coalesced across warp
        float xv1 = xp[c * 4096 + 64];
        unsigned long long x0 = pk2(xv0, xv0);
        unsigned long long x1 = pk2(xv1, xv1);
#pragma unroll
        for (int k = 0; k < 12; k++) {
            ulonglong2 w = ws[c][k];          // broadcast LDS.128
            a0[2*k]   = fma2(w.x, x0, a0[2*k]);
            a0[2*k+1] = fma2(w.y, x0, a0[2*k+1]);
            a1[2*k]   = fma2(w.x, x1, a1[2*k]);
            a1[2*k+1] = fma2(w.y, x1, a1[2*k+1]);
        }
    }

    float f0[48], f1[48];
#pragma unroll
    for (int k = 0; k < 24; k++) {
        upk2(a0[k], f0[2*k], f0[2*k+1]);
        upk2(a1[k], f1[2*k], f1[2*k+1]);
    }

    // delta: both pixels of this column
    float* dp0 = g_delta + ((size_t)(b * 4096 + row0 * 64 + xcol)) * 8;
#pragma unroll
    for (int j = 0; j < 8; j++) {
        dp0[j]          = f0[j] + bias[j];
        dp0[64 * 8 + j] = f1[j] + bias[j];
    }

    // pool within this column, then merge with partner column via shfl
    float pm[40];
#pragma unroll
    for (int j = 0; j < 40; j++) {
        float v = fmaxf(f0[8 + j], f1[8 + j]);
        pm[j] = fmaxf(v, __shfl_xor_sync(0xffffffffu, v, 1));
    }
    // bias commutes with max; col0 writes phi + g[0..15], col1 writes g[16..31]
    float* gp = g_gP + ((size_t)(b * 1024 + q)) * 32;
    if (col == 0) {
#pragma unroll
        for (int j = 0; j < 8; j++)
            g_phiP[(b * 8 + j) * 1024 + q] = pm[j] + bias[8 + j];
#pragma unroll
        for (int j = 0; j < 16; j++)
            gp[j] = pm[8 + j] + bias[16 + j];
    } else {
#pragma unroll
        for (int j = 16; j < 32; j++)
            gp[j] = pm[8 + j] + bias[16 + j];
    }
}

// ---------------------------------------------------------------------------
// Kernel 2: fused attention + final conv + residual.
// grid (8,16): 512 queries/CTA, 256 threads, 2 q/thread.
// Key loop blocked by 8: phase A computes 8 independent QK->exp chains,
// phase B does 8 independent PV rank-1 updates. All smem addresses are
// base+immediate; no register rotation. log2e folded into q (bare ex2).
// Single-pass softmax without max subtraction (scores O(10), exp safe in fp32).
// ---------------------------------------------------------------------------
__global__ __launch_bounds__(256, 1) void attn_kernel(
    const float* __restrict__ x,
    const float* __restrict__ w_last, const float* __restrict__ b_last,
    const float* __restrict__ gamma,  float* __restrict__ out)
{
    extern __shared__ float sm[];
    float* Vsm = sm;              // 1024*32 = 32768 floats (128 KB)
    float* Ksm = sm + 32768;      // 1024*8  =  8192 floats ( 32 KB)
    float* wl  = sm + 40960;      // 64*32   =  2048 floats (  8 KB)
    float* bl  = sm + 43008;      // 64

    const int tid = threadIdx.x;
    const int b   = blockIdx.y;

    {   // V: [1024][32] straight copy
        const float4* src = (const float4*)(g_gP + (size_t)b * 32768);
        float4* dst = (float4*)Vsm;
        for (int i = tid; i < 8192; i += 256) dst[i] = src[i];
    }
    // K gather with the reference's (1,0,2,3)-transpose batch mixing:
    // K[b][j][m] = phiP[(b*8+j)%16][(b*8+j)/16][m]
#pragma unroll
    for (int j = 0; j < 8; j++) {
        int idx = b * 8 + j;
        const float* src = g_phiP + (size_t)((idx & 15) * 8 + (idx >> 4)) * 1024;
        for (int m = tid; m < 1024; m += 256) Ksm[m * 8 + j] = src[m];
    }
    for (int i = tid; i < 2048; i += 256) wl[i] = w_last[i];
    if (tid < 64) bl[tid] = b_last[tid];
    __syncthreads();

    const int q0 = blockIdx.x * 512 + tid;
    const int q1 = q0 + 256;
    const ulonglong2* dq0 = (const ulonglong2*)(g_delta + ((size_t)b * 4096 + q0) * 8);
    const ulonglong2* dq1 = (const ulonglong2*)(g_delta + ((size_t)b * 4096 + q1) * 8);
    // fold log2(e) into q so exp(score) == ex2(dot)
    const unsigned long long L2E = pk2(1.4426950408889634f, 1.4426950408889634f);
    ulonglong2 qa, qb, qc, qd;
    { ulonglong2 r0 = dq0[0], r1 = dq0[1], r2 = dq1[0], r3 = dq1[1];
      qa.x = mul2(r0.x, L2E); qa.y = mul2(r0.y, L2E);
      qb.x = mul2(r1.x, L2E); qb.y = mul2(r1.y, L2E);
      qc.x = mul2(r2.x, L2E); qc.y = mul2(r2.y, L2E);
      qd.x = mul2(r3.x, L2E); qd.y = mul2(r3.y, L2E); }

    unsigned long long acc0[16], acc1[16];   // 2 x 32 fp32 accumulators as f32x2 pairs
#pragma unroll
    for (int k = 0; k < 16; k++) { acc0[k] = 0ull; acc1[k] = 0ull; }
    float l0 = 0.f, l1 = 0.f;

    for (int mb = 0; mb < 1024; mb += 8) {
        const ulonglong2* Kp = (const ulonglong2*)Ksm + 2 * mb;   // 8 keys, imm offsets
        const ulonglong2* Vp = (const ulonglong2*)Vsm + 8 * mb;

        float e0[8], e1[8];
        // Phase A: 8 independent QK -> exp chains
#pragma unroll
        for (int u = 0; u < 8; u++) {
            ulonglong2 kA = Kp[2 * u], kB = Kp[2 * u + 1];        // broadcast LDS.128
            unsigned long long p0 = mul2(qa.x, kA.x);
            p0 = fma2(qa.y, kA.y, p0);
            p0 = fma2(qb.x, kB.x, p0);
            p0 = fma2(qb.y, kB.y, p0);
            unsigned long long p1 = mul2(qc.x, kA.x);
            p1 = fma2(qc.y, kA.y, p1);
            p1 = fma2(qd.x, kB.x, p1);
            p1 = fma2(qd.y, kB.y, p1);
            float s0a, s0b, s1a, s1b;
            upk2(p0, s0a, s0b);
            upk2(p1, s1a, s1b);
            e0[u] = ex2(s0a + s0b);
            e1[u] = ex2(s1a + s1b);
        }
        // Phase B: 8 independent PV rank-1 updates
#pragma unroll
        for (int u = 0; u < 8; u++) {
            unsigned long long e0p = pk2(e0[u], e0[u]);
            unsigned long long e1p = pk2(e1[u], e1[u]);
            l0 += e0[u];
            l1 += e1[u];
            const ulonglong2* v = Vp + 8 * u;                     // broadcast LDS.128 x8
#pragma unroll
            for (int t = 0; t < 8; t++) {
                ulonglong2 vv = v[t];
                acc0[2*t]   = fma2(e0p, vv.x, acc0[2*t]);
                acc0[2*t+1] = fma2(e0p, vv.y, acc0[2*t+1]);
                acc1[2*t]   = fma2(e1p, vv.x, acc1[2*t]);
                acc1[2*t+1] = fma2(e1p, vv.y, acc1[2*t+1]);
            }
        }
    }

    // Fused epilogue: out[b,c,n] = gamma*(dot32(O_n, w_last[c]) + b_last[c]) + x[b,c,n]
    // with O = acc / l  =>  (gamma/l)*dot(acc, w) + gamma*b_last + x
    const float gm  = gamma[0];
    const float gi0 = __fdividef(gm, l0);
    const float gi1 = __fdividef(gm, l1);
    const float* xb = x   + (size_t)b * 262144;
    float*       ob = out + (size_t)b * 262144;
    const ulonglong2* wl2 = (const ulonglong2*)wl;

    for (int c = 0; c < 64; c++) {
        const ulonglong2* wr = wl2 + c * 8;
        ulonglong2 w0 = wr[0];
        unsigned long long s0 = mul2(acc0[0], w0.x);
        unsigned long long s1 = mul2(acc1[0], w0.x);
        s0 = fma2(acc0[1], w0.y, s0);
        s1 = fma2(acc1[1], w0.y, s1);
#pragma unroll
        for (int t = 1; t < 8; t++) {
            ulonglong2 w = wr[t];
            s0 = fma2(acc0[2*t],   w.x, s0);
            s1 = fma2(acc1[2*t],   w.x, s1);
            s0 = fma2(acc0[2*t+1], w.y, s0);
            s1 = fma2(acc1[2*t+1], w.y, s1);
        }
        float r0a, r0b, r1a, r1b;
        upk2(s0, r0a, r0b);
        upk2(s1, r1a, r1b);
        float base = gm * bl[c];
        ob[c * 4096 + q0] = fmaf(gi0, r0a + r0b, base + xb[c * 4096 + q0]);
        ob[c * 4096 + q1] = fmaf(gi1, r1a + r1b, base + xb[c * 4096 + q1]);
    }
}

// ---------------------------------------------------------------------------
extern "C" void kernel_launch(void* const* d_in, const int* in_sizes, int n_in,
                              void* d_out, int out_size)
{
    const float* x  = (const float*)d_in[0];
    const float* wd = (const float*)d_in[1];
    const float* bd = (const float*)d_in[2];
    const float* wp = (const float*)d_in[3];
    const float* bp = (const float*)d_in[4];
    const float* wg = (const float*)d_in[5];
    const float* bg = (const float*)d_in[6];
    const float* wl = (const float*)d_in[7];
    const float* bl = (const float*)d_in[8];
    const float* gm = (const float*)d_in[9];

    conv_pool_kernel<<<dim3(8, 16), 256>>>(x, wd, bd, wp, bp, wg, bg);

    const int shm = (32768 + 8192 + 2048 + 64) * 4;  // 172288 B
    cudaFuncSetAttribute(attn_kernel, cudaFuncAttributeMaxDynamicSharedMemorySize, shm);
    attn_kernel<<<dim3(8, 16), 256, shm>>>(x, wl, bl, gm, (float*)d_out);
}